// round 16
// baseline (speedup 1.0000x reference)
#include <cuda_runtime.h>
#include <cuda_fp16.h>
#include <cstdint>

#define NE    8
#define NTOK  4096
#define DH    2048
#define DE    1024
#define MAXTILES 104
#define MAXROWS  (MAXTILES*128)   // 13312

// ---------------- device-global scratch (static, no allocation) ----------------
__device__ __align__(16) __half g_Xh[(size_t)MAXROWS*DH];
__device__ __align__(16) __half g_Hh[(size_t)MAXROWS*DE];

__device__ int   g_tok[NE*NTOK];
__device__ float g_wt [NE*NTOK];
__device__ int   g_cnt[NE];
__device__ int   g_off[10];
__device__ float g_rowwt[MAXROWS];
__device__ int   g_row2tok[MAXROWS];  // padded row -> token (-1 = pad)
__device__ int   g_tile_e[MAXTILES];
__device__ int   g_ntiles, g_total;

// ---------------- helpers ----------------
__device__ __forceinline__ void cp16s(uint32_t s, const void* g) {
    asm volatile("cp.async.cg.shared.global [%0], [%1], 16;\n" :: "r"(s), "l"(g));
}
__device__ __forceinline__ void cp_commit() { asm volatile("cp.async.commit_group;\n"); }
template<int N> __device__ __forceinline__ void cp_wait() {
    asm volatile("cp.async.wait_group %0;\n" :: "n"(N));
}
__device__ __forceinline__ void ldm4(uint32_t* r, uint32_t a) {
    asm volatile("ldmatrix.sync.aligned.m8n8.x4.shared.b16 {%0,%1,%2,%3},[%4];\n"
                 : "=r"(r[0]), "=r"(r[1]), "=r"(r[2]), "=r"(r[3]) : "r"(a));
}
__device__ __forceinline__ void ldm4t(uint32_t* r, uint32_t a) {
    asm volatile("ldmatrix.sync.aligned.m8n8.x4.trans.shared.b16 {%0,%1,%2,%3},[%4];\n"
                 : "=r"(r[0]), "=r"(r[1]), "=r"(r[2]), "=r"(r[3]) : "r"(a));
}
__device__ __forceinline__ void mma16816(float* c, const uint32_t* a, const uint32_t* b) {
    asm volatile(
        "mma.sync.aligned.m16n8k16.row.col.f32.f16.f16.f32 "
        "{%0,%1,%2,%3},{%4,%5,%6,%7},{%8,%9},{%0,%1,%2,%3};\n"
        : "+f"(c[0]), "+f"(c[1]), "+f"(c[2]), "+f"(c[3])
        : "r"(a[0]), "r"(a[1]), "r"(a[2]), "r"(a[3]), "r"(b[0]), "r"(b[1]));
}
__device__ __forceinline__ void redadd(float* p, float v) {
    asm volatile("red.global.add.f32 [%0], %1;" :: "l"(p), "f"(v) : "memory");
}
__device__ __forceinline__ uint4 pack8(float4 a, float4 b) {
    __half2 h0 = __floats2half2_rn(a.x, a.y);
    __half2 h1 = __floats2half2_rn(a.z, a.w);
    __half2 h2 = __floats2half2_rn(b.x, b.y);
    __half2 h3 = __floats2half2_rn(b.z, b.w);
    uint4 o;
    o.x = *(uint32_t*)&h0; o.y = *(uint32_t*)&h1;
    o.z = *(uint32_t*)&h2; o.w = *(uint32_t*)&h3;
    return o;
}
__device__ __forceinline__ void sts128(uint32_t a, uint4 v) {
    asm volatile("st.shared.v4.b32 [%0],{%1,%2,%3,%4};"
                 :: "r"(a), "r"(v.x), "r"(v.y), "r"(v.z), "r"(v.w) : "memory");
}

// ---------------- 1. init ----------------
__global__ void init_kernel() { if (threadIdx.x < NE) g_cnt[threadIdx.x] = 0; }

// ---------------- 2. router: warp per token ----------------
__global__ void router_kernel(const float* __restrict__ x, const float* __restrict__ Wg) {
    int warp = threadIdx.x >> 5, lane = threadIdx.x & 31;
    int t = blockIdx.x * 8 + warp;
    if (t >= NTOK) return;
    const float* xr = x + (size_t)t * DH;
    float acc[NE];
#pragma unroll
    for (int e = 0; e < NE; e++) acc[e] = 0.f;
    for (int d = lane; d < DH; d += 32) {
        float xv = xr[d];
        const float* wr = Wg + (size_t)d * NE;
#pragma unroll
        for (int e = 0; e < NE; e++) acc[e] += xv * wr[e];
    }
#pragma unroll
    for (int o = 16; o; o >>= 1)
#pragma unroll
        for (int e = 0; e < NE; e++) acc[e] += __shfl_down_sync(0xFFFFFFFFu, acc[e], o);
    if (lane == 0) {
        float m = acc[0];
#pragma unroll
        for (int e = 1; e < NE; e++) m = fmaxf(m, acc[e]);
        float p[NE], s = 0.f;
#pragma unroll
        for (int e = 0; e < NE; e++) { p[e] = __expf(acc[e] - m); s += p[e]; }
        float inv = 1.f / s;
#pragma unroll
        for (int e = 0; e < NE; e++) p[e] *= inv;
        int e0 = 0; float b0 = p[0];
#pragma unroll
        for (int e = 1; e < NE; e++) if (p[e] > b0) { b0 = p[e]; e0 = e; }
        int e1 = -1; float b1 = -1.f;
#pragma unroll
        for (int e = 0; e < NE; e++) if (e != e0 && p[e] > b1) { b1 = p[e]; e1 = e; }
        int s0 = atomicAdd(&g_cnt[e0], 1);
        g_tok[e0*NTOK + s0] = t; g_wt[e0*NTOK + s0] = b0;
        int s1 = atomicAdd(&g_cnt[e1], 1);
        g_tok[e1*NTOK + s1] = t; g_wt[e1*NTOK + s1] = b1;
    }
}

// ---------------- 3. offsets + tile map ----------------
__global__ void offsets_kernel() {
    if (threadIdx.x != 0) return;
    int off = 0, tc = 0;
    for (int e = 0; e < 9; e++) {
        g_off[e] = off;
        int c = (e < NE) ? g_cnt[e] : NTOK;
        int nt = (c + 127) >> 7;
        for (int i = 0; i < nt; i++) g_tile_e[tc + i] = e;
        tc += nt; off += nt << 7;
    }
    g_off[9] = off; g_ntiles = tc; g_total = off;
}

// ---------------- 4. gather + fp32->fp16 (+ row->token map) ----------------
__global__ void gather_kernel(const float* __restrict__ x) {
    int r = blockIdx.x;
    if (r >= g_total) return;
    int e = 8;
#pragma unroll
    for (int i = 0; i < 9; i++) if (r < g_off[i+1]) { e = i; break; }
    int s = r - g_off[e];
    int t = -1; float wt = 0.f;
    if (e < NE) {
        if (s < g_cnt[e]) { t = g_tok[e*NTOK + s]; wt = g_wt[e*NTOK + s]; }
    } else { t = s; wt = 1.f; }
    if (threadIdx.x == 0) { g_rowwt[r] = wt; g_row2tok[r] = t; }
    __half* dh = g_Xh + (size_t)r * DH;
    if (t >= 0) {
        const float4* src = (const float4*)(x + (size_t)t * DH);
        for (int i = threadIdx.x; i < DH/4; i += blockDim.x) {
            float4 v = src[i];
            ((__half2*)dh)[i*2+0] = __halves2half2(__float2half(v.x), __float2half(v.y));
            ((__half2*)dh)[i*2+1] = __halves2half2(__float2half(v.z), __float2half(v.w));
        }
    } else {
        uint4 z = {0,0,0,0};
        for (int i = threadIdx.x; i < DH/8; i += blockDim.x) ((uint4*)dh)[i] = z;
    }
}

// ---------------- 5. grouped GEMM: fp16 mma.sync; B loaded as fp32 from the
// ORIGINAL weight tensors and converted in-register (no wconv pass).
// A: 3-stage cp.async ring (fp16 scratch). B: register-staged LDG->cvt->STS,
// 2-slot smem ring; one __syncthreads per k-chunk provides all ordering.
// FUSE=1: 128M x 128N, A=Xh (K=2048), B=gate&up; epilogue silu(g)*u*wt -> Hh
// FUSE=0: 128M x 256N, A=Hh (K=1024), B=down;    epilogue red.add -> out[token]
#define SMROW 80    // A smem row bytes (32 halfs + 8 pad)

template<bool FUSE>
__global__ void __launch_bounds__(512, 1) gemm_hmma(
    float* __restrict__ out,
    const float* __restrict__ W0r, const float* __restrict__ W0s,
    const float* __restrict__ W1r, const float* __restrict__ W1s) {
    int tm = blockIdx.y;
    if (tm >= g_ntiles) return;
    constexpr int K  = FUSE ? DH : DE;      // A K-dim
    constexpr int NF = FUSE ? DE : DH;      // B row stride (N total)
    constexpr int BN = FUSE ? 128 : 256;    // block N
    constexpr int WN = FUSE ? 32 : 64;      // warp tile N
    constexpr int NFRAG = WN / 8;           // 4 or 8
    constexpr int PG = WN / 16;             // ldm4t groups: 2 or 4
    constexpr int KC = K / 32;
    constexpr int BROW = BN * 2 + 16;       // 272 or 528
    constexpr int ASTAGE = 128 * SMROW;     // 10240
    constexpr int OFFB0 = 3 * ASTAGE;       // 30720
    constexpr int BMAT = 32 * BROW;         // 8704 or 16896
    constexpr int BSLOT = (FUSE ? 2 : 1) * BMAT;
    int e = g_tile_e[tm];
    int row0 = tm * 128;
    int n0 = blockIdx.x * BN;

    extern __shared__ char smem[];
    uint32_t sbase = (uint32_t)__cvta_generic_to_shared(smem);
    const int tid = threadIdx.x, lane = tid & 31, warp = tid >> 5;
    const int wm = (warp >> 2) * 32, wn = (warp & 3) * WN;
    const int ar = lane & 15, ac = (lane >> 4) << 3;
    const int bkk = (lane & 7) + (((lane >> 3) & 1) << 3);
    const int bn8 = (lane >> 4) << 3;
    const int gp = lane >> 2, tq = lane & 3;

    // A pointers (fp16 scratch)
    const __half* pa = (FUSE ? g_Xh : g_Hh) + (size_t)row0 * K
                       + (size_t)(tid >> 2) * K + (tid & 3) * 8;
    const uint32_t sA = (tid >> 2) * SMROW + (tid & 3) * 16;

    // B pointers (fp32 originals; expert 8 = shared)
    const float* src0 = (e < NE) ? (W0r + (size_t)e * DE * DH) : W0s;
    const float* pb0f;
    const float* pb1f = nullptr;
    if (FUSE) {
        pb0f = src0 + (size_t)(tid >> 4) * NF + n0 + (tid & 15) * 8;
        const float* src1 = (e < NE) ? (W1r + (size_t)e * DE * DH) : W1s;
        pb1f = src1 + (size_t)(tid >> 4) * NF + n0 + (tid & 15) * 8;
    } else {
        pb0f = src0 + (size_t)(tid >> 5) * NF + n0 + (tid & 31) * 8;
    }
    const uint32_t sB = FUSE ? (tid >> 4) * BROW + (tid & 15) * 16
                             : (tid >> 5) * BROW + (tid & 31) * 16;

    float4 rb0, rb1, rb2, rb3;
    auto ldgB = [&]() {
        rb0 = *(const float4*)pb0f;
        rb1 = *(const float4*)(pb0f + 4);
        if (FUSE) {
            rb2 = *(const float4*)pb1f;
            rb3 = *(const float4*)(pb1f + 4);
            pb1f += (size_t)32 * NF;
        } else {
            rb2 = *(const float4*)(pb0f + (size_t)16 * NF);
            rb3 = *(const float4*)(pb0f + (size_t)16 * NF + 4);
        }
        pb0f += (size_t)32 * NF;
    };
    auto stsB = [&](int slot) {
        uint32_t b = sbase + OFFB0 + slot * BSLOT + sB;
        sts128(b, pack8(rb0, rb1));
        if (FUSE) sts128(b + BMAT, pack8(rb2, rb3));
        else      sts128(b + 16 * BROW, pack8(rb2, rb3));
    };
    auto loadA = [&](int slot) { cp16s(sbase + slot * ASTAGE + sA, pa); pa += 32; };

    float acc0[2][NFRAG][4], acc1[FUSE ? 2 : 1][FUSE ? NFRAG : 1][4];
#pragma unroll
    for (int i = 0; i < 2; i++)
#pragma unroll
    for (int j = 0; j < NFRAG; j++)
#pragma unroll
    for (int k = 0; k < 4; k++) {
        acc0[i][j][k] = 0.f;
        if (FUSE) acc1[i][j][k] = 0.f;
    }

    // prologue: B0 -> smem slot0, B1 staged in regs; A0, A1 via cp.async
    ldgB();
    stsB(0);
    ldgB();
    loadA(0); cp_commit();
    loadA(1); cp_commit();

    for (int kc = 0; kc < KC; kc++) {
        cp_wait<1>();            // A(kc) arrived
        __syncthreads();         // all sts for B(kc) drained; prior compute done
        if (kc + 1 < KC) stsB((kc + 1) & 1);   // regs hold B(kc+1)
        if (kc + 2 < KC) { ldgB(); loadA((kc + 2) % 3); }
        cp_commit();             // one group per iteration keeps wait<1> aligned
        uint32_t baseA = sbase + (kc % 3) * ASTAGE;
        uint32_t baseB = sbase + OFFB0 + (kc & 1) * BSLOT;
#pragma unroll
        for (int kk = 0; kk < 32; kk += 16) {
            uint32_t ah[2][4];
#pragma unroll
            for (int mt = 0; mt < 2; mt++)
                ldm4(ah[mt], baseA + (wm + mt*16 + ar)*SMROW + (kk + ac)*2);
            uint32_t b0[NFRAG][2], b1[FUSE ? NFRAG : 1][2];
#pragma unroll
            for (int p = 0; p < PG; p++) {
                uint32_t baddr = baseB + (kk + bkk)*BROW + (wn + p*16 + bn8)*2;
                uint32_t r4[4];
                ldm4t(r4, baddr);
                b0[2*p][0]=r4[0]; b0[2*p][1]=r4[1]; b0[2*p+1][0]=r4[2]; b0[2*p+1][1]=r4[3];
                if (FUSE) {
                    ldm4t(r4, baddr + BMAT);
                    b1[2*p][0]=r4[0]; b1[2*p][1]=r4[1]; b1[2*p+1][0]=r4[2]; b1[2*p+1][1]=r4[3];
                }
            }
#pragma unroll
            for (int mt = 0; mt < 2; mt++)
#pragma unroll
            for (int nt = 0; nt < NFRAG; nt++) {
                mma16816(acc0[mt][nt], ah[mt], b0[nt]);
                if (FUSE) mma16816(acc1[mt][nt], ah[mt], b1[nt]);
            }
        }
    }

    // ---------------- epilogue ----------------
    if (FUSE) {
        float wt[2][2];
#pragma unroll
        for (int mt = 0; mt < 2; mt++)
#pragma unroll
        for (int jj = 0; jj < 2; jj++)
            wt[mt][jj] = g_rowwt[row0 + wm + mt*16 + gp + jj*8];
#pragma unroll
        for (int mt = 0; mt < 2; mt++)
#pragma unroll
        for (int nt = 0; nt < NFRAG; nt++)
#pragma unroll
        for (int jj = 0; jj < 2; jj++) {
            int r = row0 + wm + mt*16 + gp + jj*8;
            int c = n0 + wn + nt*8 + tq*2;
            float g0 = acc0[mt][nt][jj*2], g1 = acc0[mt][nt][jj*2+1];
            float u0 = acc1[mt][nt][jj*2], u1 = acc1[mt][nt][jj*2+1];
            float w  = wt[mt][jj];
            float h0 = (g0 / (1.f + __expf(-g0))) * u0 * w;
            float h1 = (g1 / (1.f + __expf(-g1))) * u1 * w;
            *(__half2*)(g_Hh + (size_t)r*DE + c) =
                __halves2half2(__float2half(h0), __float2half(h1));
        }
    } else {
        // scatter-reduce directly into out[token] (h already carries routing wt)
        int tok[2][2];
#pragma unroll
        for (int mt = 0; mt < 2; mt++)
#pragma unroll
        for (int jj = 0; jj < 2; jj++)
            tok[mt][jj] = g_row2tok[row0 + wm + mt*16 + gp + jj*8];
#pragma unroll
        for (int mt = 0; mt < 2; mt++)
#pragma unroll
        for (int jj = 0; jj < 2; jj++) {
            int t = tok[mt][jj];
            if (t < 0) continue;
            float* orow = out + (size_t)t * DH + n0 + wn + tq*2;
#pragma unroll
            for (int nt = 0; nt < NFRAG; nt++) {
                redadd(orow + nt*8,     acc0[mt][nt][jj*2]);
                redadd(orow + nt*8 + 1, acc0[mt][nt][jj*2+1]);
            }
        }
    }
}

// ---------------- launch ----------------
extern "C" void kernel_launch(void* const* d_in, const int* in_sizes, int n_in,
                              void* d_out, int out_size) {
    const float* x     = (const float*)d_in[0];
    const float* Wg    = (const float*)d_in[1];
    const float* Wgate = (const float*)d_in[2];
    const float* Wup   = (const float*)d_in[3];
    const float* Wdown = (const float*)d_in[4];
    const float* Wsg   = (const float*)d_in[5];
    const float* Wsu   = (const float*)d_in[6];
    const float* Wsd   = (const float*)d_in[7];
    float* out = (float*)d_out;

    // FUSE: 3*10240 + 2*2*8704  = 65536
    // DOWN: 3*10240 + 2*1*16896 = 64512
    const int FUSE_SMEM = 3*(128*SMROW) + 2*2*(32*(128*2+16));
    const int DOWN_SMEM = 3*(128*SMROW) + 2*1*(32*(256*2+16));
    cudaFuncSetAttribute(gemm_hmma<true>,  cudaFuncAttributeMaxDynamicSharedMemorySize, FUSE_SMEM);
    cudaFuncSetAttribute(gemm_hmma<false>, cudaFuncAttributeMaxDynamicSharedMemorySize, DOWN_SMEM);

    cudaMemsetAsync(out, 0, (size_t)NTOK * DH * sizeof(float), 0);
    init_kernel<<<1, 32>>>();
    router_kernel<<<NTOK/8, 256>>>(x, Wg);
    offsets_kernel<<<1, 32>>>();
    gather_kernel<<<MAXROWS, 256>>>(x);
    gemm_hmma<true><<<dim3(DE/128, MAXTILES), 512, FUSE_SMEM>>>(nullptr, Wgate, Wsg, Wup, Wsu);
    gemm_hmma<false><<<dim3(DH/256, MAXTILES), 512, DOWN_SMEM>>>(out, Wdown, Wsd, nullptr, nullptr);
}

// round 17
// speedup vs baseline: 1.1762x; 1.1762x over previous
#include <cuda_runtime.h>
#include <cuda_fp16.h>
#include <cstdint>

#define NE    8
#define NTOK  4096
#define DH    2048
#define DE    1024
#define MAXTILES 104
#define MAXROWS  (MAXTILES*128)   // 13312

// ---------------- device-global scratch (static, no allocation) ----------------
__device__ __align__(16) __half g_Xh[(size_t)NTOK*DH];      // token-indexed (dense)
__device__ __align__(16) __half g_Hh[(size_t)MAXROWS*DE];   // row-indexed
// weights fp16, NATURAL layout [e][K][N]. 9th "expert" = shared.
__device__ __align__(16) __half g_Wgh[(size_t)9*DE*DH];
__device__ __align__(16) __half g_Wuh[(size_t)9*DE*DH];
__device__ __align__(16) __half g_Wdh[(size_t)9*DE*DH];

__device__ int   g_tok[NE*NTOK];
__device__ float g_wt [NE*NTOK];
__device__ int   g_cnt[NE];
__device__ int   g_off[10];
__device__ float g_rowwt[MAXROWS];
__device__ int   g_row2tok[MAXROWS];  // padded row -> token (-1 = pad)
__device__ int   g_tile_e[MAXTILES];
__device__ int   g_ntiles, g_total;

// ---------------- helpers ----------------
__device__ __forceinline__ void cp16s(uint32_t s, const void* g) {
    asm volatile("cp.async.cg.shared.global [%0], [%1], 16;\n" :: "r"(s), "l"(g));
}
__device__ __forceinline__ void cp_commit() { asm volatile("cp.async.commit_group;\n"); }
template<int N> __device__ __forceinline__ void cp_wait() {
    asm volatile("cp.async.wait_group %0;\n" :: "n"(N));
}
__device__ __forceinline__ void ldm4(uint32_t* r, uint32_t a) {
    asm volatile("ldmatrix.sync.aligned.m8n8.x4.shared.b16 {%0,%1,%2,%3},[%4];\n"
                 : "=r"(r[0]), "=r"(r[1]), "=r"(r[2]), "=r"(r[3]) : "r"(a));
}
__device__ __forceinline__ void ldm4t(uint32_t* r, uint32_t a) {
    asm volatile("ldmatrix.sync.aligned.m8n8.x4.trans.shared.b16 {%0,%1,%2,%3},[%4];\n"
                 : "=r"(r[0]), "=r"(r[1]), "=r"(r[2]), "=r"(r[3]) : "r"(a));
}
__device__ __forceinline__ void mma16816(float* c, const uint32_t* a, const uint32_t* b) {
    asm volatile(
        "mma.sync.aligned.m16n8k16.row.col.f32.f16.f16.f32 "
        "{%0,%1,%2,%3},{%4,%5,%6,%7},{%8,%9},{%0,%1,%2,%3};\n"
        : "+f"(c[0]), "+f"(c[1]), "+f"(c[2]), "+f"(c[3])
        : "r"(a[0]), "r"(a[1]), "r"(a[2]), "r"(a[3]), "r"(b[0]), "r"(b[1]));
}
__device__ __forceinline__ void redadd2(float* p, float a, float b) {
    asm volatile("red.global.add.v2.f32 [%0], {%1,%2};" :: "l"(p), "f"(a), "f"(b) : "memory");
}

// ---------------- 1. dense x fp32->fp16 convert (+ cnt init) ----------------
__global__ void xconv_kernel(const float* __restrict__ x) {
    if (blockIdx.x == 0 && threadIdx.x < NE) g_cnt[threadIdx.x] = 0;
    int t = blockIdx.x;
    const float4* src = (const float4*)(x + (size_t)t * DH);
    __half* dh = g_Xh + (size_t)t * DH;
    for (int i = threadIdx.x; i < DH/4; i += blockDim.x) {
        float4 v = src[i];
        ((__half2*)dh)[i*2+0] = __halves2half2(__float2half(v.x), __float2half(v.y));
        ((__half2*)dh)[i*2+1] = __halves2half2(__float2half(v.z), __float2half(v.w));
    }
}

// ---------------- 2. router: warp per token ----------------
__global__ void router_kernel(const float* __restrict__ x, const float* __restrict__ Wg) {
    int warp = threadIdx.x >> 5, lane = threadIdx.x & 31;
    int t = blockIdx.x * 8 + warp;
    if (t >= NTOK) return;
    const float* xr = x + (size_t)t * DH;
    float acc[NE];
#pragma unroll
    for (int e = 0; e < NE; e++) acc[e] = 0.f;
    for (int d = lane; d < DH; d += 32) {
        float xv = xr[d];
        const float* wr = Wg + (size_t)d * NE;
#pragma unroll
        for (int e = 0; e < NE; e++) acc[e] += xv * wr[e];
    }
#pragma unroll
    for (int o = 16; o; o >>= 1)
#pragma unroll
        for (int e = 0; e < NE; e++) acc[e] += __shfl_down_sync(0xFFFFFFFFu, acc[e], o);
    if (lane == 0) {
        float m = acc[0];
#pragma unroll
        for (int e = 1; e < NE; e++) m = fmaxf(m, acc[e]);
        float p[NE], s = 0.f;
#pragma unroll
        for (int e = 0; e < NE; e++) { p[e] = __expf(acc[e] - m); s += p[e]; }
        float inv = 1.f / s;
#pragma unroll
        for (int e = 0; e < NE; e++) p[e] *= inv;
        int e0 = 0; float b0 = p[0];
#pragma unroll
        for (int e = 1; e < NE; e++) if (p[e] > b0) { b0 = p[e]; e0 = e; }
        int e1 = -1; float b1 = -1.f;
#pragma unroll
        for (int e = 0; e < NE; e++) if (e != e0 && p[e] > b1) { b1 = p[e]; e1 = e; }
        int s0 = atomicAdd(&g_cnt[e0], 1);
        g_tok[e0*NTOK + s0] = t; g_wt[e0*NTOK + s0] = b0;
        int s1 = atomicAdd(&g_cnt[e1], 1);
        g_tok[e1*NTOK + s1] = t; g_wt[e1*NTOK + s1] = b1;
    }
}

// ---------------- 3. offsets + tile map ----------------
__global__ void offsets_kernel() {
    if (threadIdx.x != 0) return;
    int off = 0, tc = 0;
    for (int e = 0; e < 9; e++) {
        g_off[e] = off;
        int c = (e < NE) ? g_cnt[e] : NTOK;
        int nt = (c + 127) >> 7;
        for (int i = 0; i < nt; i++) g_tile_e[tc + i] = e;
        tc += nt; off += nt << 7;
    }
    g_off[9] = off; g_ntiles = tc; g_total = off;
}

// ---------------- 4. rowmap: padded row -> (token, weight) ----------------
__global__ void rowmap_kernel() {
    int r = blockIdx.x * blockDim.x + threadIdx.x;
    if (r >= g_total) return;
    int e = 8;
#pragma unroll
    for (int i = 0; i < 9; i++) if (r < g_off[i+1]) { e = i; break; }
    int s = r - g_off[e];
    int t = -1; float wt = 0.f;
    if (e < NE) {
        if (s < g_cnt[e]) { t = g_tok[e*NTOK + s]; wt = g_wt[e*NTOK + s]; }
    } else { t = s; wt = 1.f; }
    g_rowwt[r] = wt;
    g_row2tok[r] = t;
}

// ---------------- 5. weight fp32->fp16 convert (merged, 3 matrices) ----------
__global__ void wconv_kernel(const float* __restrict__ Wgate, const float* __restrict__ Wsg,
                             const float* __restrict__ Wup,   const float* __restrict__ Wsu,
                             const float* __restrict__ Wdown, const float* __restrict__ Wsd) {
    constexpr size_t KN = (size_t)DE * DH;
    int w = blockIdx.y;
    const float* Wr = (w==0) ? Wgate : (w==1) ? Wup : Wdown;
    const float* Ws = (w==0) ? Wsg   : (w==1) ? Wsu : Wsd;
    __half* dst = ((w==0) ? g_Wgh : (w==1) ? g_Wuh : g_Wdh) + (size_t)blockIdx.z * KN;
    const float* src = (blockIdx.z < NE) ? (Wr + (size_t)blockIdx.z * KN) : Ws;
    int gid = blockIdx.x * blockDim.x + threadIdx.x;   // KN/4 threads
    float4 v = ((const float4*)src)[gid];
    uint2 o;
    __half2 h0 = __halves2half2(__float2half(v.x), __float2half(v.y));
    __half2 h1 = __halves2half2(__float2half(v.z), __float2half(v.w));
    o.x = *(uint32_t*)&h0; o.y = *(uint32_t*)&h1;
    ((uint2*)dst)[gid] = o;
}

// ---------------- 6. grouped GEMM: fp16 mma.sync, row-major B via ldmatrix.trans
// FUSE=1: 128M x 128N, A=g_Xh via row->token indirection (K=2048), B=gate&up;
//         epilogue silu(g)*u*wt -> Hh  (pad rows: alias token 0, wt=0 => H=0)
// FUSE=0: 128M x 256N, A=Hh row-indexed (K=1024), B=down;
//         epilogue red.add.v2 -> out[token]
#define SMROW 80    // A smem row bytes (32 halfs + 8 pad)
#define NSTG  3

template<bool FUSE>
__global__ void __launch_bounds__(512, 1) gemm_hmma(float* __restrict__ out) {
    int tm = blockIdx.y;
    if (tm >= g_ntiles) return;
    constexpr int K  = FUSE ? DH : DE;      // A K-dim
    constexpr int NF = FUSE ? DE : DH;      // B row stride (N total)
    constexpr int BN = FUSE ? 128 : 256;    // block N
    constexpr int WN = FUSE ? 32 : 64;      // warp tile N
    constexpr int NFRAG = WN / 8;           // 4 or 8
    constexpr int PG = WN / 16;             // ldm4t groups: 2 or 4
    constexpr int KC = K / 32;
    constexpr int BROW = BN * 2 + 16;       // 272 or 528
    constexpr int OFFB0 = 128 * SMROW;      // 10240
    constexpr int BMAT = 32 * BROW;         // 8704 or 16896
    constexpr int STAGE = OFFB0 + (FUSE ? 2 : 1) * BMAT;
    int e = g_tile_e[tm];
    int row0 = tm * 128;
    int n0 = blockIdx.x * BN;

    extern __shared__ char smem[];
    uint32_t sbase = (uint32_t)__cvta_generic_to_shared(smem);
    const int tid = threadIdx.x, lane = tid & 31, warp = tid >> 5;
    const int wm = (warp >> 2) * 32, wn = (warp & 3) * WN;
    const int ar = lane & 15, ac = (lane >> 4) << 3;
    const int bkk = (lane & 7) + (((lane >> 3) & 1) << 3);
    const int bn8 = (lane >> 4) << 3;
    const int gp = lane >> 2, tq = lane & 3;

    // A pointer: FUSE uses row->token indirection into dense g_Xh
    const __half* pa;
    if (FUSE) {
        int t = g_row2tok[row0 + (tid >> 2)];
        if (t < 0) t = 0;                      // pad: any finite data (wt=0 kills it)
        pa = g_Xh + (size_t)t * DH + (tid & 3) * 8;
    } else {
        pa = g_Hh + (size_t)row0 * K + (size_t)(tid >> 2) * K + (tid & 3) * 8;
    }
    size_t wbase = (size_t)e * DE * DH + n0;
    const __half* pb0;
    const __half* pb1 = nullptr;
    if (FUSE) {
        pb0 = g_Wgh + wbase + (size_t)(tid >> 4) * NF + (tid & 15) * 8;
        pb1 = g_Wuh + wbase + (size_t)(tid >> 4) * NF + (tid & 15) * 8;
    } else {
        pb0 = g_Wdh + wbase + (size_t)(tid >> 5) * NF + (tid & 31) * 8;
    }
    const uint32_t sA = (tid >> 2) * SMROW + (tid & 3) * 16;
    const uint32_t sB = FUSE ? (tid >> 4) * BROW + (tid & 15) * 16
                             : (tid >> 5) * BROW + (tid & 31) * 16;

    auto load_stage = [&](int buf) {
        uint32_t base = sbase + buf * STAGE;
        cp16s(base + sA, pa); pa += 32;
        cp16s(base + OFFB0 + sB, pb0);
        if (FUSE) {
            cp16s(base + OFFB0 + BMAT + sB, pb1);
            pb1 += (size_t)32 * NF;
        } else {
            cp16s(base + OFFB0 + sB + 16 * BROW, pb0 + (size_t)16 * NF);
        }
        pb0 += (size_t)32 * NF;
    };

    float acc0[2][NFRAG][4], acc1[FUSE ? 2 : 1][FUSE ? NFRAG : 1][4];
#pragma unroll
    for (int i = 0; i < 2; i++)
#pragma unroll
    for (int j = 0; j < NFRAG; j++)
#pragma unroll
    for (int k = 0; k < 4; k++) {
        acc0[i][j][k] = 0.f;
        if (FUSE) acc1[i][j][k] = 0.f;
    }

    load_stage(0); cp_commit();
    load_stage(1); cp_commit();
    int buf = 0;
    for (int kc = 0; kc < KC; kc++) {
        cp_wait<1>();
        __syncthreads();
        if (kc + 2 < KC) { load_stage((buf + 2 >= NSTG) ? buf + 2 - NSTG : buf + 2); cp_commit(); }
        else             { cp_commit(); }
        uint32_t base = sbase + buf * STAGE;
#pragma unroll
        for (int kk = 0; kk < 32; kk += 16) {
            uint32_t ah[2][4];
#pragma unroll
            for (int mt = 0; mt < 2; mt++)
                ldm4(ah[mt], base + (wm + mt*16 + ar)*SMROW + (kk + ac)*2);
            uint32_t b0[NFRAG][2], b1[FUSE ? NFRAG : 1][2];
#pragma unroll
            for (int p = 0; p < PG; p++) {
                uint32_t baddr = base + OFFB0 + (kk + bkk)*BROW + (wn + p*16 + bn8)*2;
                uint32_t r4[4];
                ldm4t(r4, baddr);
                b0[2*p][0]=r4[0]; b0[2*p][1]=r4[1]; b0[2*p+1][0]=r4[2]; b0[2*p+1][1]=r4[3];
                if (FUSE) {
                    ldm4t(r4, baddr + BMAT);
                    b1[2*p][0]=r4[0]; b1[2*p][1]=r4[1]; b1[2*p+1][0]=r4[2]; b1[2*p+1][1]=r4[3];
                }
            }
#pragma unroll
            for (int mt = 0; mt < 2; mt++)
#pragma unroll
            for (int nt = 0; nt < NFRAG; nt++) {
                mma16816(acc0[mt][nt], ah[mt], b0[nt]);
                if (FUSE) mma16816(acc1[mt][nt], ah[mt], b1[nt]);
            }
        }
        buf = (buf + 1 == NSTG) ? 0 : buf + 1;
    }

    // ---------------- epilogue ----------------
    if (FUSE) {
        float wt[2][2];
#pragma unroll
        for (int mt = 0; mt < 2; mt++)
#pragma unroll
        for (int jj = 0; jj < 2; jj++)
            wt[mt][jj] = g_rowwt[row0 + wm + mt*16 + gp + jj*8];
#pragma unroll
        for (int mt = 0; mt < 2; mt++)
#pragma unroll
        for (int nt = 0; nt < NFRAG; nt++)
#pragma unroll
        for (int jj = 0; jj < 2; jj++) {
            int r = row0 + wm + mt*16 + gp + jj*8;
            int c = n0 + wn + nt*8 + tq*2;
            float g0 = acc0[mt][nt][jj*2], g1 = acc0[mt][nt][jj*2+1];
            float u0 = acc1[mt][nt][jj*2], u1 = acc1[mt][nt][jj*2+1];
            float w  = wt[mt][jj];
            float h0 = (g0 / (1.f + __expf(-g0))) * u0 * w;
            float h1 = (g1 / (1.f + __expf(-g1))) * u1 * w;
            *(__half2*)(g_Hh + (size_t)r*DE + c) =
                __halves2half2(__float2half(h0), __float2half(h1));
        }
    } else {
        // scatter-reduce directly into out[token] (h already carries routing wt)
        int tok[2][2];
#pragma unroll
        for (int mt = 0; mt < 2; mt++)
#pragma unroll
        for (int jj = 0; jj < 2; jj++)
            tok[mt][jj] = g_row2tok[row0 + wm + mt*16 + gp + jj*8];
#pragma unroll
        for (int mt = 0; mt < 2; mt++)
#pragma unroll
        for (int jj = 0; jj < 2; jj++) {
            int t = tok[mt][jj];
            if (t < 0) continue;
            float* orow = out + (size_t)t * DH + n0 + wn + tq*2;
#pragma unroll
            for (int nt = 0; nt < NFRAG; nt++)
                redadd2(orow + nt*8, acc0[mt][nt][jj*2], acc0[mt][nt][jj*2+1]);
        }
    }
}

// ---------------- launch ----------------
extern "C" void kernel_launch(void* const* d_in, const int* in_sizes, int n_in,
                              void* d_out, int out_size) {
    const float* x     = (const float*)d_in[0];
    const float* Wg    = (const float*)d_in[1];
    const float* Wgate = (const float*)d_in[2];
    const float* Wup   = (const float*)d_in[3];
    const float* Wdown = (const float*)d_in[4];
    const float* Wsg   = (const float*)d_in[5];
    const float* Wsu   = (const float*)d_in[6];
    const float* Wsd   = (const float*)d_in[7];
    float* out = (float*)d_out;

    const int FUSE_SMEM = NSTG * (128*SMROW + 2*(32*(128*2+16)));   // 82944
    const int DOWN_SMEM = NSTG * (128*SMROW + 1*(32*(256*2+16)));   // 81408
    cudaFuncSetAttribute(gemm_hmma<true>,  cudaFuncAttributeMaxDynamicSharedMemorySize, FUSE_SMEM);
    cudaFuncSetAttribute(gemm_hmma<false>, cudaFuncAttributeMaxDynamicSharedMemorySize, DOWN_SMEM);

    cudaMemsetAsync(out, 0, (size_t)NTOK * DH * sizeof(float), 0);
    xconv_kernel<<<NTOK, 256>>>(x);
    router_kernel<<<NTOK/8, 256>>>(x, Wg);
    offsets_kernel<<<1, 32>>>();
    rowmap_kernel<<<(MAXROWS + 255)/256, 256>>>();
    wconv_kernel<<<dim3((DE*DH/4)/256, 3, 9), 256>>>(Wgate, Wsg, Wup, Wsu, Wdown, Wsd);
    gemm_hmma<true><<<dim3(DE/128, MAXTILES), 512, FUSE_SMEM>>>(nullptr);
    gemm_hmma<false><<<dim3(DH/256, MAXTILES), 512, DOWN_SMEM>>>(out);
}